// round 12
// baseline (speedup 1.0000x reference)
#include <cuda_runtime.h>
#include <cuda_bf16.h>
#include <math.h>
#include <stdint.h>

// Problem constants (fixed by the reference)
#define N0   100000
#define N1   200000
#define NNZE 400000
#define DIN  256
#define DOUT 256

#define N0PAD 100096                 // 782 * 128
#define SCAN_B 1024
#define NB_SCAN ((N1 + SCAN_B - 1) / SCAN_B)   // 196

// ---------------------------------------------------------------------------
// Scratch (allocation-free __device__ globals)
// ---------------------------------------------------------------------------
__device__ float g_msg[(size_t)N0 * DOUT];     // 102.4 MB
__device__ int   g_count[N1];
__device__ int   g_off[N1 + 1];
__device__ int   g_cursor[N1];
__device__ int   g_scol[NNZE];
__device__ float g_sval[NNZE];
__device__ int   g_bsum[256];
__device__ int   g_boff[256];

// W^T pre-split into bf16 hi/lo (tiny: 256 KB total)
__device__ __align__(16) __nv_bfloat16 g_wt_hi[DOUT * DIN];           // W^T [n][k]
__device__ __align__(16) __nv_bfloat16 g_wt_lo[DOUT * DIN];

// ---------------------------------------------------------------------------
// Helpers (all baseline PTX, compiles for compute_103)
// ---------------------------------------------------------------------------
__device__ __forceinline__ uint32_t smem_u32(const void* p) {
    uint32_t a;
    asm("{ .reg .u64 t; cvta.to.shared.u64 t, %1; cvt.u32.u64 %0, t; }"
        : "=r"(a) : "l"(p));
    return a;
}
// 64B-row swizzle for B tiles: XOR 16B-column bits [5:4] with row bits [8:7]
__device__ __forceinline__ uint32_t swz(uint32_t o) { return o ^ ((o >> 3) & 0x30); }

#define CP16(dst, src) \
    asm volatile("cp.async.cg.shared.global [%0], [%1], 16;" \
                 :: "r"(dst), "l"(src))
// 8-byte form with src-size (n==0 -> zero-fill for pad rows)
#define CP8Z(dst, src, n) \
    asm volatile("cp.async.ca.shared.global [%0], [%1], 8, %2;" \
                 :: "r"(dst), "l"(src), "r"(n))
#define CP_COMMIT() asm volatile("cp.async.commit_group;")
#define CP_WAIT2()  asm volatile("cp.async.wait_group 2;")
#define CP_WAIT0()  asm volatile("cp.async.wait_group 0;")

#define LDSM4(r0, r1, r2, r3, addr) \
    asm volatile("ldmatrix.sync.aligned.m8n8.x4.shared.b16 {%0,%1,%2,%3}, [%4];" \
                 : "=r"(r0), "=r"(r1), "=r"(r2), "=r"(r3) : "r"(addr))

#define LDS64F(x, y, addr) \
    asm volatile("ld.shared.v2.f32 {%0, %1}, [%2];" \
                 : "=f"(x), "=f"(y) : "r"(addr))

#define MMA_BF16(d, a, b) \
    asm volatile("mma.sync.aligned.m16n8k16.row.col.f32.bf16.bf16.f32 " \
                 "{%0,%1,%2,%3}, {%4,%5,%6,%7}, {%8,%9}, {%0,%1,%2,%3};" \
                 : "+f"((d)[0]), "+f"((d)[1]), "+f"((d)[2]), "+f"((d)[3]) \
                 : "r"((a)[0]), "r"((a)[1]), "r"((a)[2]), "r"((a)[3]), \
                   "r"((b)[0]), "r"((b)[1]))

// Stage layout (32 KB per stage, 3 stages = 96 KB, 2 CTAs/SM):
//   [0    :16384) A fp32 staging: 128 rows x 128 B, 8B units XOR-swizzled
//   [16384:24576) B hi bf16 (swizzled 64B rows)
//   [24576:32768) B lo bf16
#define SM_STG(s)  ((s) * 32768)
#define SM_BH(s)   ((s) * 32768 + 16384)
#define SM_BL(s)   ((s) * 32768 + 24576)
#define GEMM_SMEM  98304
#define KCHUNKS 8        // 256 / 32

// ---------------------------------------------------------------------------
// W prep: transpose + split fp32 -> bf16 hi/lo (tiny, one launch).
// ---------------------------------------------------------------------------
__global__ __launch_bounds__(256)
void wt_prep_kernel(const float* __restrict__ W)
{
    int idx = blockIdx.x * blockDim.x + threadIdx.x;
    if (idx >= DIN * DOUT) return;
    int n = idx >> 8;
    int k = idx & 255;
    float v = W[(size_t)k * DOUT + n];
    __nv_bfloat16 hi = __float2bfloat16(v);
    __nv_bfloat16 lo = __float2bfloat16(v - __bfloat162float(hi));
    g_wt_hi[n * DIN + k] = hi;
    g_wt_lo[n * DIN + k] = lo;
}

// ---------------------------------------------------------------------------
// Tensor-core (mma.sync bf16, split 3-pass) GEMM, register-fused A split:
//   g_msg[128 x 128 per CTA] = x_0 @ W
// Block 128x128, BK=32, 8 warps (2x4), warp tile 64x32.
// A is read from fp32 SMEM staging DIRECTLY in mma fragment layout
// (ld.shared.v2.f32) and converted to bf16 hi+lo in registers — no smem
// convert pass, no A LDSM. B uses pre-split bf16 + ldmatrix (unchanged).
// 3-stage cp.async pipeline, 2 barriers/chunk, 2 CTAs/SM.
// ---------------------------------------------------------------------------
__global__ __launch_bounds__(256, 2)
void gemm_mma_kernel(const float* __restrict__ x0)
{
    extern __shared__ char smem[];
    const uint32_t sb = smem_u32(smem);
    const int tid  = threadIdx.x;
    const int lane = tid & 31;
    const int warp = tid >> 5;
    const int wm = (warp & 1) * 64;       // warp m offset in block tile
    const int wn = (warp >> 1) * 32;      // warp n offset
    const int blockRow = blockIdx.y * 128;
    const int blockCol = blockIdx.x * 128;

    float acc[4][4][4];
    #pragma unroll
    for (int i = 0; i < 4; i++)
        #pragma unroll
        for (int j = 0; j < 4; j++)
            #pragma unroll
            for (int r = 0; r < 4; r++) acc[i][j][r] = 0.f;

    // --- async fp32 A chunk -> staging (8B units, XOR-swizzled for
    //     conflict-free fragment-layout reads)
    auto issueA = [&](int chunk) {
        uint32_t s0 = sb + SM_STG(chunk % 3);
        #pragma unroll
        for (int rep = 0; rep < 8; rep++) {
            int slot = tid + rep * 256;          // 0..2047 8B units
            int row  = slot >> 4;                // 0..127
            int u8   = slot & 15;                // 8B unit within 128B row
            int grow = blockRow + row;
            int ok   = (grow < N0) ? 8 : 0;
            const float* src = x0 + (size_t)(ok ? grow : 0) * DIN + chunk * 32 + u8 * 2;
            uint32_t dst = s0 + row * 128 + ((u8 ^ ((row & 3) << 2)) * 8);
            CP8Z(dst, (const char*)src, ok);
        }
    };
    // --- async bf16 B hi/lo chunk (swizzled 64B rows, unchanged)
    auto issueB = [&](int chunk) {
        uint32_t bh = sb + SM_BH(chunk % 3);
        uint32_t bl = sb + SM_BL(chunk % 3);
        #pragma unroll
        for (int rep = 0; rep < 2; rep++) {
            int slot = tid + rep * 256;          // 0..511
            int row  = slot >> 2;                // 0..127
            int u    = slot & 3;                 // 16B unit within 64B row
            uint32_t so = swz((uint32_t)(row * 64 + u * 16));
            size_t gb = (size_t)(blockCol + row) * DIN + chunk * 32 + u * 8;
            CP16(bh + so, (const char*)(g_wt_hi + gb));
            CP16(bl + so, (const char*)(g_wt_lo + gb));
        }
    };

    issueA(0); issueB(0); CP_COMMIT();
    issueA(1); issueB(1); CP_COMMIT();

    const int rx4 = ((lane >> 2) & 3) << 2;      // (row&3)<<2 swizzle term

    for (int c = 0; c < KCHUNKS; c++) {
        if (c + 2 < KCHUNKS) { issueA(c + 2); issueB(c + 2); }
        CP_COMMIT();
        CP_WAIT2();          // chunk c's group complete
        __syncthreads();     // cross-thread visibility of cp.async data

        uint32_t astg = sb + SM_STG(c % 3);
        uint32_t bhs  = sb + SM_BH(c % 3);
        uint32_t bls  = sb + SM_BL(c % 3);

        #pragma unroll
        for (int kk = 0; kk < 2; kk++) {
            // ---- A fragments: fp32 LDS in fragment layout -> bf16 hi+lo regs.
            uint32_t ah[4][4], al[4][4];
            {
                int rbase  = wm + (lane >> 2);
                int u8base = kk * 8 + (lane & 3);
                #pragma unroll
                for (int mt = 0; mt < 4; mt++) {
                    #pragma unroll
                    for (int half = 0; half < 2; half++) {
                        #pragma unroll
                        for (int ro = 0; ro < 2; ro++) {
                            int rr = rbase + mt * 16 + ro * 8;
                            uint32_t u8 = (uint32_t)(u8base + half * 4);
                            uint32_t addr = astg + rr * 128 + ((u8 ^ rx4) * 8);
                            float dx, dy;
                            LDS64F(dx, dy, addr);
                            uint32_t h;
                            asm("cvt.rn.bf16x2.f32 %0, %1, %2;"
                                : "=r"(h) : "f"(dy), "f"(dx));
                            float hx = __uint_as_float(h << 16);
                            float hy = __uint_as_float(h & 0xffff0000u);
                            uint32_t l;
                            asm("cvt.rn.bf16x2.f32 %0, %1, %2;"
                                : "=r"(l) : "f"(dy - hy), "f"(dx - hx));
                            int fi = half * 2 + ro;   // a0..a3
                            ah[mt][fi] = h;
                            al[mt][fi] = l;
                        }
                    }
                }
            }

            // ---- B fragments (hi) via ldmatrix (unchanged layout)
            uint32_t b_kb   = (uint32_t)(kk * 32 + (((lane >> 3) & 1) << 4));
            uint32_t b_roff = (uint32_t)(((lane & 7) + ((lane >> 4) << 3)) * 64);
            uint32_t bf[4][2];
            #pragma unroll
            for (int np = 0; np < 2; np++) {
                uint32_t off = swz((uint32_t)((wn + np * 16) * 64) + b_roff + b_kb);
                LDSM4(bf[2*np][0], bf[2*np][1], bf[2*np+1][0], bf[2*np+1][1],
                      bhs + off);
            }
            // pass 1: A-hi * B-hi
            #pragma unroll
            for (int mt = 0; mt < 4; mt++)
                #pragma unroll
                for (int nt = 0; nt < 4; nt++)
                    MMA_BF16(acc[mt][nt], ah[mt], bf[nt]);
            // pass 3: A-lo * B-hi   (B-hi then dead)
            #pragma unroll
            for (int mt = 0; mt < 4; mt++)
                #pragma unroll
                for (int nt = 0; nt < 4; nt++)
                    MMA_BF16(acc[mt][nt], al[mt], bf[nt]);
            // reload bf[] with B-lo
            #pragma unroll
            for (int np = 0; np < 2; np++) {
                uint32_t off = swz((uint32_t)((wn + np * 16) * 64) + b_roff + b_kb);
                LDSM4(bf[2*np][0], bf[2*np][1], bf[2*np+1][0], bf[2*np+1][1],
                      bls + off);
            }
            // pass 2: A-hi * B-lo
            #pragma unroll
            for (int mt = 0; mt < 4; mt++)
                #pragma unroll
                for (int nt = 0; nt < 4; nt++)
                    MMA_BF16(acc[mt][nt], ah[mt], bf[nt]);
        }
        __syncthreads();     // protect stage before iter c+1 issues into it
    }
    CP_WAIT0();

    // Epilogue: c-fragment -> g_msg fp32
    #pragma unroll
    for (int mt = 0; mt < 4; mt++) {
        #pragma unroll
        for (int nt = 0; nt < 4; nt++) {
            int r0  = blockRow + wm + mt * 16 + (lane >> 2);
            int col = blockCol + wn + nt * 8 + (lane & 3) * 2;
            if (r0 < N0)
                *(float2*)(g_msg + (size_t)r0 * DOUT + col) =
                    make_float2(acc[mt][nt][0], acc[mt][nt][1]);
            if (r0 + 8 < N0)
                *(float2*)(g_msg + (size_t)(r0 + 8) * DOUT + col) =
                    make_float2(acc[mt][nt][2], acc[mt][nt][3]);
        }
    }
}

// ---------------------------------------------------------------------------
// CSR build
// ---------------------------------------------------------------------------
__global__ __launch_bounds__(256)
void zero_count_kernel()
{
    int i = blockIdx.x * blockDim.x + threadIdx.x;
    if (i < N1) g_count[i] = 0;
}

__global__ __launch_bounds__(256)
void count_kernel(const int* __restrict__ rows)
{
    int e = blockIdx.x * blockDim.x + threadIdx.x;
    if (e < NNZE) atomicAdd(&g_count[rows[e]], 1);
}

__global__ __launch_bounds__(SCAN_B)
void scan1_kernel()
{
    __shared__ int s[SCAN_B];
    int tid = threadIdx.x;
    int i = blockIdx.x * SCAN_B + tid;
    int v = (i < N1) ? g_count[i] : 0;
    s[tid] = v;
    __syncthreads();
    #pragma unroll
    for (int off = 1; off < SCAN_B; off <<= 1) {
        int t = (tid >= off) ? s[tid - off] : 0;
        __syncthreads();
        s[tid] += t;
        __syncthreads();
    }
    if (i < N1) g_off[i] = s[tid] - v;
    if (tid == SCAN_B - 1) g_bsum[blockIdx.x] = s[tid];
}

__global__ __launch_bounds__(256)
void scan2_kernel()
{
    __shared__ int s[256];
    int tid = threadIdx.x;
    int v = (tid < NB_SCAN) ? g_bsum[tid] : 0;
    s[tid] = v;
    __syncthreads();
    #pragma unroll
    for (int off = 1; off < 256; off <<= 1) {
        int t = (tid >= off) ? s[tid - off] : 0;
        __syncthreads();
        s[tid] += t;
        __syncthreads();
    }
    if (tid < NB_SCAN) g_boff[tid] = s[tid] - v;
}

__global__ __launch_bounds__(SCAN_B)
void scan3_kernel()
{
    int tid = threadIdx.x;
    int i = blockIdx.x * SCAN_B + tid;
    if (i < N1) {
        int val = g_off[i] + g_boff[blockIdx.x];
        g_off[i]    = val;
        g_cursor[i] = val;
    }
    if (i == 0) g_off[N1] = NNZE;
}

__global__ __launch_bounds__(256)
void fill_kernel(const int* __restrict__ rows,
                 const int* __restrict__ cols,
                 const float* __restrict__ vals)
{
    int e = blockIdx.x * blockDim.x + threadIdx.x;
    if (e < NNZE) {
        int pos = atomicAdd(&g_cursor[rows[e]], 1);
        g_scol[pos] = cols[e];
        g_sval[pos] = vals[e];
    }
}

// ---------------------------------------------------------------------------
// Aggregation: one warp per output row. Atomic-free, ELU fused, single write.
// ---------------------------------------------------------------------------
__global__ __launch_bounds__(256)
void aggregate_kernel(float* __restrict__ out)
{
    int row  = (blockIdx.x * blockDim.x + threadIdx.x) >> 5;
    int lane = threadIdx.x & 31;
    if (row >= N1) return;

    int beg = g_off[row];
    int end = g_off[row + 1];

    float4 acc0 = make_float4(0.f, 0.f, 0.f, 0.f);
    float4 acc1 = make_float4(0.f, 0.f, 0.f, 0.f);

    for (int e = beg; e < end; e++) {
        int   c = g_scol[e];
        float v = g_sval[e];
        const float4* src = (const float4*)(g_msg + (size_t)c * DOUT);
        float4 p0 = src[lane];
        float4 p1 = src[lane + 32];
        acc0.x = fmaf(v, p0.x, acc0.x);
        acc0.y = fmaf(v, p0.y, acc0.y);
        acc0.z = fmaf(v, p0.z, acc0.z);
        acc0.w = fmaf(v, p0.w, acc0.w);
        acc1.x = fmaf(v, p1.x, acc1.x);
        acc1.y = fmaf(v, p1.y, acc1.y);
        acc1.z = fmaf(v, p1.z, acc1.z);
        acc1.w = fmaf(v, p1.w, acc1.w);
    }

    acc0.x = acc0.x > 0.f ? acc0.x : expm1f(acc0.x);
    acc0.y = acc0.y > 0.f ? acc0.y : expm1f(acc0.y);
    acc0.z = acc0.z > 0.f ? acc0.z : expm1f(acc0.z);
    acc0.w = acc0.w > 0.f ? acc0.w : expm1f(acc0.w);
    acc1.x = acc1.x > 0.f ? acc1.x : expm1f(acc1.x);
    acc1.y = acc1.y > 0.f ? acc1.y : expm1f(acc1.y);
    acc1.z = acc1.z > 0.f ? acc1.z : expm1f(acc1.z);
    acc1.w = acc1.w > 0.f ? acc1.w : expm1f(acc1.w);

    float4* dst = (float4*)(out + (size_t)row * DOUT);
    dst[lane]      = acc0;
    dst[lane + 32] = acc1;
}

// ---------------------------------------------------------------------------
// Launch. Inputs: x_0, x_1(unused), nb_rows, nb_cols, nb_vals, weight.
// Output: float32 [N1, DOUT]. Serial launches (stream fork reverted — it was
// neutral in R11); gemm kept at launch position 4 for the ncu capture window.
// ---------------------------------------------------------------------------
extern "C" void kernel_launch(void* const* d_in, const int* in_sizes, int n_in,
                              void* d_out, int out_size)
{
    const float* x_0     = (const float*)d_in[0];
    const int*   nb_rows = (const int*)  d_in[2];
    const int*   nb_cols = (const int*)  d_in[3];
    const float* nb_vals = (const float*)d_in[4];
    const float* weight  = (const float*)d_in[5];
    float*       out     = (float*)d_out;

    static bool attr_done = false;
    if (!attr_done) {
        cudaFuncSetAttribute(gemm_mma_kernel,
                             cudaFuncAttributeMaxDynamicSharedMemorySize, GEMM_SMEM);
        attr_done = true;
    }

    // (1) W prep (tiny).
    wt_prep_kernel<<<(DIN * DOUT + 255) / 256, 256>>>(weight);
    // (2) (3) independent CSR-prep launches (keep gemm at position 4).
    zero_count_kernel<<<(N1 + 255) / 256, 256>>>();
    count_kernel<<<(NNZE + 255) / 256, 256>>>(nb_rows);
    // (4) Tensor-core GEMM, register-fused A split: grid (2, 782).
    dim3 ggrid(DOUT / 128, N0PAD / 128);
    gemm_mma_kernel<<<ggrid, 256, GEMM_SMEM>>>(x_0);
    // (5..8) CSR build (independent of GEMM result).
    scan1_kernel<<<NB_SCAN, SCAN_B>>>();
    scan2_kernel<<<1, 256>>>();
    scan3_kernel<<<NB_SCAN, SCAN_B>>>();
    fill_kernel<<<(NNZE + 255) / 256, 256>>>(nb_rows, nb_cols, nb_vals);
    // (9) Fused gather + segment-sum + ELU, one warp per row, no atomics.
    int gblocks = (N1 * 32 + 255) / 256;
    aggregate_kernel<<<gblocks, 256>>>(out);
}

// round 14
// speedup vs baseline: 1.0657x; 1.0657x over previous
#include <cuda_runtime.h>
#include <cuda_bf16.h>
#include <cuda_fp16.h>
#include <math.h>
#include <stdint.h>

// Problem constants (fixed by the reference)
#define N0   100000
#define N1   200000
#define NNZE 400000
#define DIN  256
#define DOUT 256

#define N0PAD 100096                 // 782 * 128
#define SCAN_B 1024
#define NB_SCAN ((N1 + SCAN_B - 1) / SCAN_B)   // 196

// ---------------------------------------------------------------------------
// Scratch (allocation-free __device__ globals)
// ---------------------------------------------------------------------------
__device__ __align__(16) __half g_msg_h[(size_t)N0 * DOUT];   // 51.2 MB (fp16)
__device__ int   g_count[N1];
__device__ int   g_off[N1 + 1];
__device__ int   g_cursor[N1];
__device__ int   g_scol[NNZE];
__device__ float g_sval[NNZE];
__device__ int   g_bsum[256];
__device__ int   g_boff[256];

// W^T pre-split into bf16 hi/lo (tiny: 256 KB total)
__device__ __align__(16) __nv_bfloat16 g_wt_hi[DOUT * DIN];           // W^T [n][k]
__device__ __align__(16) __nv_bfloat16 g_wt_lo[DOUT * DIN];

// ---------------------------------------------------------------------------
// Helpers (all baseline PTX, compiles for compute_103)
// ---------------------------------------------------------------------------
__device__ __forceinline__ uint32_t smem_u32(const void* p) {
    uint32_t a;
    asm("{ .reg .u64 t; cvta.to.shared.u64 t, %1; cvt.u32.u64 %0, t; }"
        : "=r"(a) : "l"(p));
    return a;
}
// 64B-row swizzle: XOR 16B-column bits [5:4] with row bits [8:7]
__device__ __forceinline__ uint32_t swz(uint32_t o) { return o ^ ((o >> 3) & 0x30); }

#define CP16(dst, src) \
    asm volatile("cp.async.cg.shared.global [%0], [%1], 16;" \
                 :: "r"(dst), "l"(src))
// src-size form: n==0 -> zero-fill (pad rows)
#define CP16Z(dst, src, n) \
    asm volatile("cp.async.cg.shared.global [%0], [%1], 16, %2;" \
                 :: "r"(dst), "l"(src), "r"(n))
#define CP_COMMIT() asm volatile("cp.async.commit_group;")
#define CP_WAIT1()  asm volatile("cp.async.wait_group 1;")
#define CP_WAIT0()  asm volatile("cp.async.wait_group 0;")

#define LDSM4(r0, r1, r2, r3, addr) \
    asm volatile("ldmatrix.sync.aligned.m8n8.x4.shared.b16 {%0,%1,%2,%3}, [%4];" \
                 : "=r"(r0), "=r"(r1), "=r"(r2), "=r"(r3) : "r"(addr))

#define MMA_BF16(d, a, b) \
    asm volatile("mma.sync.aligned.m16n8k16.row.col.f32.bf16.bf16.f32 " \
                 "{%0,%1,%2,%3}, {%4,%5,%6,%7}, {%8,%9}, {%0,%1,%2,%3};" \
                 : "+f"((d)[0]), "+f"((d)[1]), "+f"((d)[2]), "+f"((d)[3]) \
                 : "r"((a)[0]), "r"((a)[1]), "r"((a)[2]), "r"((a)[3]), \
                   "r"((b)[0]), "r"((b)[1]))

// Stage layout (48 KB per stage, 2 stages = 96 KB):
//   [0      :16384) A fp32 staging (128 rows x 32 cols, linear 16B slots)
//   [16384  :24576) A hi bf16 (swizzled 64B rows)
//   [24576  :32768) A lo bf16
//   [32768  :40960) B hi bf16
//   [40960  :49152) B lo bf16
#define SM_AF32 0
#define SM_AHI  16384
#define SM_ALO  24576
#define SM_BHI  32768
#define SM_BLO  40960
#define STAGE_BYTES 49152
#define NSTAGES 2
#define GEMM_SMEM (NSTAGES * STAGE_BYTES)     // 98304
#define KCHUNKS 8        // 256 / 32

// ---------------------------------------------------------------------------
// W prep: transpose + split fp32 -> bf16 hi/lo (tiny, one launch).
// ---------------------------------------------------------------------------
__global__ __launch_bounds__(256)
void wt_prep_kernel(const float* __restrict__ W)
{
    int idx = blockIdx.x * blockDim.x + threadIdx.x;
    if (idx >= DIN * DOUT) return;
    int n = idx >> 8;
    int k = idx & 255;
    float v = W[(size_t)k * DOUT + n];
    __nv_bfloat16 hi = __float2bfloat16(v);
    __nv_bfloat16 lo = __float2bfloat16(v - __bfloat162float(hi));
    g_wt_hi[n * DIN + k] = hi;
    g_wt_lo[n * DIN + k] = lo;
}

// ---------------------------------------------------------------------------
// Tensor-core (mma.sync bf16, split 3-pass) GEMM with FUSED A split
// (exact R10 structure — measured 113.4 us): block 128x128, BK=32, 8 warps,
// warp tile 64x32, smem convert phase, 2-stage pipeline, 2 CTAs/SM.
// Epilogue now writes g_msg as fp16 (half traffic downstream).
// ---------------------------------------------------------------------------
__global__ __launch_bounds__(256, 2)
void gemm_mma_kernel(const float* __restrict__ x0)
{
    extern __shared__ char smem[];
    const uint32_t sb = smem_u32(smem);
    const int tid  = threadIdx.x;
    const int lane = tid & 31;
    const int warp = tid >> 5;
    const int wm = (warp & 1) * 64;       // warp m offset in block tile
    const int wn = (warp >> 1) * 32;      // warp n offset
    const int blockRow = blockIdx.y * 128;
    const int blockCol = blockIdx.x * 128;

    float acc[4][4][4];
    #pragma unroll
    for (int i = 0; i < 4; i++)
        #pragma unroll
        for (int j = 0; j < 4; j++)
            #pragma unroll
            for (int r = 0; r < 4; r++) acc[i][j][r] = 0.f;

    // --- async issue of one 32-wide K chunk into stage s ---
    auto issue = [&](int chunk, int s) {
        uint32_t s0 = sb + s * STAGE_BYTES;
        // A fp32: 1024 float4 slots, linear layout, zero-fill pad rows.
        #pragma unroll
        for (int rep = 0; rep < 4; rep++) {
            int slot = tid + rep * 256;          // 0..1023
            int row  = slot >> 3;                // 0..127
            int u    = slot & 7;                 // float4 within 32-col row
            int grow = blockRow + row;
            int ok   = (grow < N0) ? 16 : 0;
            const float* src = x0 + (size_t)(ok ? grow : 0) * DIN + chunk * 32 + u * 4;
            CP16Z(s0 + SM_AF32 + slot * 16, (const char*)src, ok);
        }
        // B hi/lo: 512 float4 each, swizzled 64B rows.
        #pragma unroll
        for (int rep = 0; rep < 2; rep++) {
            int slot = tid + rep * 256;          // 0..511
            int row  = slot >> 2;                // 0..127
            int u    = slot & 3;                 // 16B unit within 64B row
            uint32_t so = swz((uint32_t)(row * 64 + u * 16));
            size_t gb = (size_t)(blockCol + row) * DIN + chunk * 32 + u * 8;
            CP16(s0 + SM_BHI + so, (const char*)(g_wt_hi + gb));
            CP16(s0 + SM_BLO + so, (const char*)(g_wt_lo + gb));
        }
    };

    issue(0, 0); CP_COMMIT();

    for (int c = 0; c < KCHUNKS; c++) {
        if (c + 1 < KCHUNKS) issue(c + 1, (c + 1) & 1);
        CP_COMMIT();            // empty group when no issue: keeps count uniform
        CP_WAIT1();             // chunk c's group complete (<=1 outstanding)
        __syncthreads();

        uint32_t base = sb + (c & 1) * STAGE_BYTES;

        // ---- Convert A fp32 staging -> bf16 hi/lo swizzled smem.
        #pragma unroll
        for (int j = 0; j < 4; j++) {
            int slot = tid + j * 256;            // 0..1023
            int row  = slot >> 3;
            int u    = slot & 7;
            float4 v = *(const float4*)(smem + (base - sb) + SM_AF32 + slot * 16);
            __nv_bfloat16 h0 = __float2bfloat16(v.x);
            __nv_bfloat16 h1 = __float2bfloat16(v.y);
            __nv_bfloat16 h2 = __float2bfloat16(v.z);
            __nv_bfloat16 h3 = __float2bfloat16(v.w);
            __nv_bfloat162 hp0(h0, h1), hp1(h2, h3);
            __nv_bfloat162 lp0(__float2bfloat16(v.x - __bfloat162float(h0)),
                               __float2bfloat16(v.y - __bfloat162float(h1)));
            __nv_bfloat162 lp1(__float2bfloat16(v.z - __bfloat162float(h2)),
                               __float2bfloat16(v.w - __bfloat162float(h3)));
            uint32_t b16 = swz((uint32_t)(row * 64 + (u >> 1) * 16)) + (u & 1) * 8;
            char* dst = smem + (base - sb);
            *(__nv_bfloat162*)(dst + SM_AHI + b16)     = hp0;
            *(__nv_bfloat162*)(dst + SM_AHI + b16 + 4) = hp1;
            *(__nv_bfloat162*)(dst + SM_ALO + b16)     = lp0;
            *(__nv_bfloat162*)(dst + SM_ALO + b16 + 4) = lp1;
        }
        __syncthreads();

        #pragma unroll
        for (int kk = 0; kk < 2; kk++) {
            // lane-dependent ldmatrix source offsets
            uint32_t a_kb   = (uint32_t)(kk * 32 + ((lane >> 4) << 4));
            uint32_t a_roff = (uint32_t)((lane & 15) * 64);
            uint32_t b_kb   = (uint32_t)(kk * 32 + (((lane >> 3) & 1) << 4));
            uint32_t b_roff = (uint32_t)(((lane & 7) + ((lane >> 4) << 3)) * 64);

            uint32_t af[4][4];        // A frags: hi for passes 1-2, lo for pass 3
            uint32_t bh[4][2], bl[4][2];

            #pragma unroll
            for (int mt = 0; mt < 4; mt++) {
                uint32_t off = swz((uint32_t)((wm + mt * 16) * 64) + a_roff + a_kb);
                LDSM4(af[mt][0], af[mt][1], af[mt][2], af[mt][3],
                      base + SM_AHI + off);
            }
            #pragma unroll
            for (int np = 0; np < 2; np++) {
                uint32_t off = swz((uint32_t)((wn + np * 16) * 64) + b_roff + b_kb);
                LDSM4(bh[2*np][0], bh[2*np][1], bh[2*np+1][0], bh[2*np+1][1],
                      base + SM_BHI + off);
            }
            // pass 1: hi * hi
            #pragma unroll
            for (int mt = 0; mt < 4; mt++)
                #pragma unroll
                for (int nt = 0; nt < 4; nt++)
                    MMA_BF16(acc[mt][nt], af[mt], bh[nt]);

            // pass 2: hi * lo
            #pragma unroll
            for (int np = 0; np < 2; np++) {
                uint32_t off = swz((uint32_t)((wn + np * 16) * 64) + b_roff + b_kb);
                LDSM4(bl[2*np][0], bl[2*np][1], bl[2*np+1][0], bl[2*np+1][1],
                      base + SM_BLO + off);
            }
            #pragma unroll
            for (int mt = 0; mt < 4; mt++)
                #pragma unroll
                for (int nt = 0; nt < 4; nt++)
                    MMA_BF16(acc[mt][nt], af[mt], bl[nt]);

            // pass 3: lo * hi  (reuse af[] for A-lo; A-hi dead)
            #pragma unroll
            for (int mt = 0; mt < 4; mt++) {
                uint32_t off = swz((uint32_t)((wm + mt * 16) * 64) + a_roff + a_kb);
                LDSM4(af[mt][0], af[mt][1], af[mt][2], af[mt][3],
                      base + SM_ALO + off);
            }
            #pragma unroll
            for (int mt = 0; mt < 4; mt++)
                #pragma unroll
                for (int nt = 0; nt < 4; nt++)
                    MMA_BF16(acc[mt][nt], af[mt], bh[nt]);
        }
        __syncthreads();    // protect this stage before iter c+1 issues into it
    }
    CP_WAIT0();

    // Epilogue: c-fragment -> g_msg fp16 (half2 stores)
    #pragma unroll
    for (int mt = 0; mt < 4; mt++) {
        #pragma unroll
        for (int nt = 0; nt < 4; nt++) {
            int r0  = blockRow + wm + mt * 16 + (lane >> 2);
            int col = blockCol + wn + nt * 8 + (lane & 3) * 2;
            if (r0 < N0)
                *(__half2*)(g_msg_h + (size_t)r0 * DOUT + col) =
                    __floats2half2_rn(acc[mt][nt][0], acc[mt][nt][1]);
            if (r0 + 8 < N0)
                *(__half2*)(g_msg_h + (size_t)(r0 + 8) * DOUT + col) =
                    __floats2half2_rn(acc[mt][nt][2], acc[mt][nt][3]);
        }
    }
}

// ---------------------------------------------------------------------------
// CSR build
// ---------------------------------------------------------------------------
__global__ __launch_bounds__(256)
void zero_count_kernel()
{
    int i = blockIdx.x * blockDim.x + threadIdx.x;
    if (i < N1) g_count[i] = 0;
}

__global__ __launch_bounds__(256)
void count_kernel(const int* __restrict__ rows)
{
    int e = blockIdx.x * blockDim.x + threadIdx.x;
    if (e < NNZE) atomicAdd(&g_count[rows[e]], 1);
}

__global__ __launch_bounds__(SCAN_B)
void scan1_kernel()
{
    __shared__ int s[SCAN_B];
    int tid = threadIdx.x;
    int i = blockIdx.x * SCAN_B + tid;
    int v = (i < N1) ? g_count[i] : 0;
    s[tid] = v;
    __syncthreads();
    #pragma unroll
    for (int off = 1; off < SCAN_B; off <<= 1) {
        int t = (tid >= off) ? s[tid - off] : 0;
        __syncthreads();
        s[tid] += t;
        __syncthreads();
    }
    if (i < N1) g_off[i] = s[tid] - v;
    if (tid == SCAN_B - 1) g_bsum[blockIdx.x] = s[tid];
}

__global__ __launch_bounds__(256)
void scan2_kernel()
{
    __shared__ int s[256];
    int tid = threadIdx.x;
    int v = (tid < NB_SCAN) ? g_bsum[tid] : 0;
    s[tid] = v;
    __syncthreads();
    #pragma unroll
    for (int off = 1; off < 256; off <<= 1) {
        int t = (tid >= off) ? s[tid - off] : 0;
        __syncthreads();
        s[tid] += t;
        __syncthreads();
    }
    if (tid < NB_SCAN) g_boff[tid] = s[tid] - v;
}

__global__ __launch_bounds__(SCAN_B)
void scan3_kernel()
{
    int tid = threadIdx.x;
    int i = blockIdx.x * SCAN_B + tid;
    if (i < N1) {
        int val = g_off[i] + g_boff[blockIdx.x];
        g_off[i]    = val;
        g_cursor[i] = val;
    }
    if (i == 0) g_off[N1] = NNZE;
}

__global__ __launch_bounds__(256)
void fill_kernel(const int* __restrict__ rows,
                 const int* __restrict__ cols,
                 const float* __restrict__ vals)
{
    int e = blockIdx.x * blockDim.x + threadIdx.x;
    if (e < NNZE) {
        int pos = atomicAdd(&g_cursor[rows[e]], 1);
        g_scol[pos] = cols[e];
        g_sval[pos] = vals[e];
    }
}

// ---------------------------------------------------------------------------
// Aggregation: one warp per output row, fp16 msg gather (16 B/lane/edge).
// Atomic-free, ELU fused, single fp32 write.
// ---------------------------------------------------------------------------
__global__ __launch_bounds__(256)
void aggregate_kernel(float* __restrict__ out)
{
    int row  = (blockIdx.x * blockDim.x + threadIdx.x) >> 5;
    int lane = threadIdx.x & 31;
    if (row >= N1) return;

    int beg = g_off[row];
    int end = g_off[row + 1];

    // Each lane owns 8 consecutive columns: [lane*8, lane*8+8)
    float acc[8];
    #pragma unroll
    for (int i = 0; i < 8; i++) acc[i] = 0.f;

    for (int e = beg; e < end; e++) {
        int   c = g_scol[e];
        float v = g_sval[e];
        const uint4* src = (const uint4*)(g_msg_h + (size_t)c * DOUT);
        uint4 p = src[lane];                    // 8 halves
        const __half2* hp = (const __half2*)&p;
        #pragma unroll
        for (int q = 0; q < 4; q++) {
            float2 f = __half22float2(hp[q]);
            acc[q * 2 + 0] = fmaf(v, f.x, acc[q * 2 + 0]);
            acc[q * 2 + 1] = fmaf(v, f.y, acc[q * 2 + 1]);
        }
    }

    #pragma unroll
    for (int i = 0; i < 8; i++)
        acc[i] = acc[i] > 0.f ? acc[i] : expm1f(acc[i]);

    float4* dst = (float4*)(out + (size_t)row * DOUT + lane * 8);
    dst[0] = make_float4(acc[0], acc[1], acc[2], acc[3]);
    dst[1] = make_float4(acc[4], acc[5], acc[6], acc[7]);
}

// ---------------------------------------------------------------------------
// Launch. Inputs: x_0, x_1(unused), nb_rows, nb_cols, nb_vals, weight.
// Output: float32 [N1, DOUT]. Serial launches; gemm at position 4 for the
// ncu capture window.
// ---------------------------------------------------------------------------
extern "C" void kernel_launch(void* const* d_in, const int* in_sizes, int n_in,
                              void* d_out, int out_size)
{
    const float* x_0     = (const float*)d_in[0];
    const int*   nb_rows = (const int*)  d_in[2];
    const int*   nb_cols = (const int*)  d_in[3];
    const float* nb_vals = (const float*)d_in[4];
    const float* weight  = (const float*)d_in[5];
    float*       out     = (float*)d_out;

    static bool attr_done = false;
    if (!attr_done) {
        cudaFuncSetAttribute(gemm_mma_kernel,
                             cudaFuncAttributeMaxDynamicSharedMemorySize, GEMM_SMEM);
        attr_done = true;
    }

    // (1) W prep (tiny).
    wt_prep_kernel<<<(DIN * DOUT + 255) / 256, 256>>>(weight);
    // (2) (3) independent CSR-prep launches (keep gemm at position 4).
    zero_count_kernel<<<(N1 + 255) / 256, 256>>>();
    count_kernel<<<(NNZE + 255) / 256, 256>>>(nb_rows);
    // (4) Tensor-core GEMM with fused A split (R10 structure): grid (2, 782).
    dim3 ggrid(DOUT / 128, N0PAD / 128);
    gemm_mma_kernel<<<ggrid, 256, GEMM_SMEM>>>(x_0);
    // (5..8) CSR build (independent of GEMM result).
    scan1_kernel<<<NB_SCAN, SCAN_B>>>();
    scan2_kernel<<<1, 256>>>();
    scan3_kernel<<<NB_SCAN, SCAN_B>>>();
    fill_kernel<<<(NNZE + 255) / 256, 256>>>(nb_rows, nb_cols, nb_vals);
    // (9) Fused gather + segment-sum + ELU, one warp per row, no atomics.
    int gblocks = (N1 * 32 + 255) / 256;
    aggregate_kernel<<<gblocks, 256>>>(out);
}

// round 16
// speedup vs baseline: 1.1228x; 1.0535x over previous
#include <cuda_runtime.h>
#include <cuda_bf16.h>
#include <cuda_fp16.h>
#include <math.h>
#include <stdint.h>

// Problem constants (fixed by the reference)
#define N0   100000
#define N1   200000
#define NNZE 400000
#define DIN  256
#define DOUT 256

#define N0PAD 100096                 // 782 * 128
#define SCAN_B 1024
#define NB_SCAN ((N1 + SCAN_B - 1) / SCAN_B)   // 196

// ---------------------------------------------------------------------------
// Scratch (allocation-free __device__ globals)
// ---------------------------------------------------------------------------
__device__ __align__(16) __half g_msg_h[(size_t)N0 * DOUT];   // 51.2 MB (fp16)
__device__ int   g_count[N1];
__device__ int   g_off[N1 + 1];
__device__ int   g_cursor[N1];
__device__ int   g_scol[NNZE];
__device__ float g_sval[NNZE];
__device__ int   g_bsum[256];
__device__ int   g_boff[256];

// W^T pre-split into bf16 hi/lo (tiny: 256 KB total)
__device__ __align__(16) __nv_bfloat16 g_wt_hi[DOUT * DIN];           // W^T [n][k]
__device__ __align__(16) __nv_bfloat16 g_wt_lo[DOUT * DIN];

// ---------------------------------------------------------------------------
// Helpers (all baseline PTX, compiles for compute_103)
// ---------------------------------------------------------------------------
__device__ __forceinline__ uint32_t smem_u32(const void* p) {
    uint32_t a;
    asm("{ .reg .u64 t; cvta.to.shared.u64 t, %1; cvt.u32.u64 %0, t; }"
        : "=r"(a) : "l"(p));
    return a;
}
// 64B-row swizzle: XOR 16B-column bits [5:4] with row bits [8:7]
__device__ __forceinline__ uint32_t swz(uint32_t o) { return o ^ ((o >> 3) & 0x30); }

#define CP16(dst, src) \
    asm volatile("cp.async.cg.shared.global [%0], [%1], 16;" \
                 :: "r"(dst), "l"(src))
// src-size form: n==0 -> zero-fill (pad rows)
#define CP16Z(dst, src, n) \
    asm volatile("cp.async.cg.shared.global [%0], [%1], 16, %2;" \
                 :: "r"(dst), "l"(src), "r"(n))
#define CP_COMMIT() asm volatile("cp.async.commit_group;")
#define CP_WAIT1()  asm volatile("cp.async.wait_group 1;")
#define CP_WAIT0()  asm volatile("cp.async.wait_group 0;")

#define LDSM4(r0, r1, r2, r3, addr) \
    asm volatile("ldmatrix.sync.aligned.m8n8.x4.shared.b16 {%0,%1,%2,%3}, [%4];" \
                 : "=r"(r0), "=r"(r1), "=r"(r2), "=r"(r3) : "r"(addr))

#define MMA_BF16(d, a, b) \
    asm volatile("mma.sync.aligned.m16n8k16.row.col.f32.bf16.bf16.f32 " \
                 "{%0,%1,%2,%3}, {%4,%5,%6,%7}, {%8,%9}, {%0,%1,%2,%3};" \
                 : "+f"((d)[0]), "+f"((d)[1]), "+f"((d)[2]), "+f"((d)[3]) \
                 : "r"((a)[0]), "r"((a)[1]), "r"((a)[2]), "r"((a)[3]), \
                   "r"((b)[0]), "r"((b)[1]))

// Stage layout (48 KB per stage, 2 stages = 96 KB):
//   [0      :16384) A fp32 staging (128 rows x 32 cols, linear 16B slots)
//   [16384  :24576) A hi bf16 (swizzled 64B rows)
//   [24576  :32768) A lo bf16
//   [32768  :40960) B hi bf16
//   [40960  :49152) B lo bf16
#define SM_AF32 0
#define SM_AHI  16384
#define SM_ALO  24576
#define SM_BHI  32768
#define SM_BLO  40960
#define STAGE_BYTES 49152
#define NSTAGES 2
#define GEMM_SMEM (NSTAGES * STAGE_BYTES)     // 98304
#define KCHUNKS 8        // 256 / 32

// ---------------------------------------------------------------------------
// W prep: transpose + split fp32 -> bf16 hi/lo (tiny, one launch).
// ---------------------------------------------------------------------------
__global__ __launch_bounds__(256)
void wt_prep_kernel(const float* __restrict__ W)
{
    int idx = blockIdx.x * blockDim.x + threadIdx.x;
    if (idx >= DIN * DOUT) return;
    int n = idx >> 8;
    int k = idx & 255;
    float v = W[(size_t)k * DOUT + n];
    __nv_bfloat16 hi = __float2bfloat16(v);
    __nv_bfloat16 lo = __float2bfloat16(v - __bfloat162float(hi));
    g_wt_hi[n * DIN + k] = hi;
    g_wt_lo[n * DIN + k] = lo;
}

// ---------------------------------------------------------------------------
// Tensor-core (mma.sync bf16, split 3-pass) GEMM with FUSED A split
// (stable R10/R14 structure — measured 113.4 us): block 128x128, BK=32,
// 8 warps, warp tile 64x32, smem convert phase, 2-stage pipeline, 2 CTAs/SM.
// Epilogue writes g_msg as fp16.
// ---------------------------------------------------------------------------
__global__ __launch_bounds__(256, 2)
void gemm_mma_kernel(const float* __restrict__ x0)
{
    extern __shared__ char smem[];
    const uint32_t sb = smem_u32(smem);
    const int tid  = threadIdx.x;
    const int lane = tid & 31;
    const int warp = tid >> 5;
    const int wm = (warp & 1) * 64;       // warp m offset in block tile
    const int wn = (warp >> 1) * 32;      // warp n offset
    const int blockRow = blockIdx.y * 128;
    const int blockCol = blockIdx.x * 128;

    float acc[4][4][4];
    #pragma unroll
    for (int i = 0; i < 4; i++)
        #pragma unroll
        for (int j = 0; j < 4; j++)
            #pragma unroll
            for (int r = 0; r < 4; r++) acc[i][j][r] = 0.f;

    // --- async issue of one 32-wide K chunk into stage s ---
    auto issue = [&](int chunk, int s) {
        uint32_t s0 = sb + s * STAGE_BYTES;
        // A fp32: 1024 float4 slots, linear layout, zero-fill pad rows.
        #pragma unroll
        for (int rep = 0; rep < 4; rep++) {
            int slot = tid + rep * 256;          // 0..1023
            int row  = slot >> 3;                // 0..127
            int u    = slot & 7;                 // float4 within 32-col row
            int grow = blockRow + row;
            int ok   = (grow < N0) ? 16 : 0;
            const float* src = x0 + (size_t)(ok ? grow : 0) * DIN + chunk * 32 + u * 4;
            CP16Z(s0 + SM_AF32 + slot * 16, (const char*)src, ok);
        }
        // B hi/lo: 512 float4 each, swizzled 64B rows.
        #pragma unroll
        for (int rep = 0; rep < 2; rep++) {
            int slot = tid + rep * 256;          // 0..511
            int row  = slot >> 2;                // 0..127
            int u    = slot & 3;                 // 16B unit within 64B row
            uint32_t so = swz((uint32_t)(row * 64 + u * 16));
            size_t gb = (size_t)(blockCol + row) * DIN + chunk * 32 + u * 8;
            CP16(s0 + SM_BHI + so, (const char*)(g_wt_hi + gb));
            CP16(s0 + SM_BLO + so, (const char*)(g_wt_lo + gb));
        }
    };

    issue(0, 0); CP_COMMIT();

    for (int c = 0; c < KCHUNKS; c++) {
        if (c + 1 < KCHUNKS) issue(c + 1, (c + 1) & 1);
        CP_COMMIT();            // empty group when no issue: keeps count uniform
        CP_WAIT1();             // chunk c's group complete (<=1 outstanding)
        __syncthreads();

        uint32_t base = sb + (c & 1) * STAGE_BYTES;

        // ---- Convert A fp32 staging -> bf16 hi/lo swizzled smem.
        #pragma unroll
        for (int j = 0; j < 4; j++) {
            int slot = tid + j * 256;            // 0..1023
            int row  = slot >> 3;
            int u    = slot & 7;
            float4 v = *(const float4*)(smem + (base - sb) + SM_AF32 + slot * 16);
            __nv_bfloat16 h0 = __float2bfloat16(v.x);
            __nv_bfloat16 h1 = __float2bfloat16(v.y);
            __nv_bfloat16 h2 = __float2bfloat16(v.z);
            __nv_bfloat16 h3 = __float2bfloat16(v.w);
            __nv_bfloat162 hp0(h0, h1), hp1(h2, h3);
            __nv_bfloat162 lp0(__float2bfloat16(v.x - __bfloat162float(h0)),
                               __float2bfloat16(v.y - __bfloat162float(h1)));
            __nv_bfloat162 lp1(__float2bfloat16(v.z - __bfloat162float(h2)),
                               __float2bfloat16(v.w - __bfloat162float(h3)));
            uint32_t b16 = swz((uint32_t)(row * 64 + (u >> 1) * 16)) + (u & 1) * 8;
            char* dst = smem + (base - sb);
            *(__nv_bfloat162*)(dst + SM_AHI + b16)     = hp0;
            *(__nv_bfloat162*)(dst + SM_AHI + b16 + 4) = hp1;
            *(__nv_bfloat162*)(dst + SM_ALO + b16)     = lp0;
            *(__nv_bfloat162*)(dst + SM_ALO + b16 + 4) = lp1;
        }
        __syncthreads();

        #pragma unroll
        for (int kk = 0; kk < 2; kk++) {
            // lane-dependent ldmatrix source offsets
            uint32_t a_kb   = (uint32_t)(kk * 32 + ((lane >> 4) << 4));
            uint32_t a_roff = (uint32_t)((lane & 15) * 64);
            uint32_t b_kb   = (uint32_t)(kk * 32 + (((lane >> 3) & 1) << 4));
            uint32_t b_roff = (uint32_t)(((lane & 7) + ((lane >> 4) << 3)) * 64);

            uint32_t af[4][4];        // A frags: hi for passes 1-2, lo for pass 3
            uint32_t bh[4][2], bl[4][2];

            #pragma unroll
            for (int mt = 0; mt < 4; mt++) {
                uint32_t off = swz((uint32_t)((wm + mt * 16) * 64) + a_roff + a_kb);
                LDSM4(af[mt][0], af[mt][1], af[mt][2], af[mt][3],
                      base + SM_AHI + off);
            }
            #pragma unroll
            for (int np = 0; np < 2; np++) {
                uint32_t off = swz((uint32_t)((wn + np * 16) * 64) + b_roff + b_kb);
                LDSM4(bh[2*np][0], bh[2*np][1], bh[2*np+1][0], bh[2*np+1][1],
                      base + SM_BHI + off);
            }
            // pass 1: hi * hi
            #pragma unroll
            for (int mt = 0; mt < 4; mt++)
                #pragma unroll
                for (int nt = 0; nt < 4; nt++)
                    MMA_BF16(acc[mt][nt], af[mt], bh[nt]);

            // pass 2: hi * lo
            #pragma unroll
            for (int np = 0; np < 2; np++) {
                uint32_t off = swz((uint32_t)((wn + np * 16) * 64) + b_roff + b_kb);
                LDSM4(bl[2*np][0], bl[2*np][1], bl[2*np+1][0], bl[2*np+1][1],
                      base + SM_BLO + off);
            }
            #pragma unroll
            for (int mt = 0; mt < 4; mt++)
                #pragma unroll
                for (int nt = 0; nt < 4; nt++)
                    MMA_BF16(acc[mt][nt], af[mt], bl[nt]);

            // pass 3: lo * hi  (reuse af[] for A-lo; A-hi dead)
            #pragma unroll
            for (int mt = 0; mt < 4; mt++) {
                uint32_t off = swz((uint32_t)((wm + mt * 16) * 64) + a_roff + a_kb);
                LDSM4(af[mt][0], af[mt][1], af[mt][2], af[mt][3],
                      base + SM_ALO + off);
            }
            #pragma unroll
            for (int mt = 0; mt < 4; mt++)
                #pragma unroll
                for (int nt = 0; nt < 4; nt++)
                    MMA_BF16(acc[mt][nt], af[mt], bh[nt]);
        }
        __syncthreads();    // protect this stage before iter c+1 issues into it
    }
    CP_WAIT0();

    // Epilogue: c-fragment -> g_msg fp16 (half2 stores)
    #pragma unroll
    for (int mt = 0; mt < 4; mt++) {
        #pragma unroll
        for (int nt = 0; nt < 4; nt++) {
            int r0  = blockRow + wm + mt * 16 + (lane >> 2);
            int col = blockCol + wn + nt * 8 + (lane & 3) * 2;
            if (r0 < N0)
                *(__half2*)(g_msg_h + (size_t)r0 * DOUT + col) =
                    __floats2half2_rn(acc[mt][nt][0], acc[mt][nt][1]);
            if (r0 + 8 < N0)
                *(__half2*)(g_msg_h + (size_t)(r0 + 8) * DOUT + col) =
                    __floats2half2_rn(acc[mt][nt][2], acc[mt][nt][3]);
        }
    }
}

// ---------------------------------------------------------------------------
// CSR build
// ---------------------------------------------------------------------------
__global__ __launch_bounds__(256)
void zero_count_kernel()
{
    int i = blockIdx.x * blockDim.x + threadIdx.x;
    if (i < N1) g_count[i] = 0;
}

__global__ __launch_bounds__(256)
void count_kernel(const int* __restrict__ rows)
{
    int e = blockIdx.x * blockDim.x + threadIdx.x;
    if (e < NNZE) atomicAdd(&g_count[rows[e]], 1);
}

__global__ __launch_bounds__(SCAN_B)
void scan1_kernel()
{
    __shared__ int s[SCAN_B];
    int tid = threadIdx.x;
    int i = blockIdx.x * SCAN_B + tid;
    int v = (i < N1) ? g_count[i] : 0;
    s[tid] = v;
    __syncthreads();
    #pragma unroll
    for (int off = 1; off < SCAN_B; off <<= 1) {
        int t = (tid >= off) ? s[tid - off] : 0;
        __syncthreads();
        s[tid] += t;
        __syncthreads();
    }
    if (i < N1) g_off[i] = s[tid] - v;
    if (tid == SCAN_B - 1) g_bsum[blockIdx.x] = s[tid];
}

__global__ __launch_bounds__(256)
void scan2_kernel()
{
    __shared__ int s[256];
    int tid = threadIdx.x;
    int v = (tid < NB_SCAN) ? g_bsum[tid] : 0;
    s[tid] = v;
    __syncthreads();
    #pragma unroll
    for (int off = 1; off < 256; off <<= 1) {
        int t = (tid >= off) ? s[tid - off] : 0;
        __syncthreads();
        s[tid] += t;
        __syncthreads();
    }
    if (tid < NB_SCAN) g_boff[tid] = s[tid] - v;
}

__global__ __launch_bounds__(SCAN_B)
void scan3_kernel()
{
    int tid = threadIdx.x;
    int i = blockIdx.x * SCAN_B + tid;
    if (i < N1) {
        int val = g_off[i] + g_boff[blockIdx.x];
        g_off[i]    = val;
        g_cursor[i] = val;
    }
    if (i == 0) g_off[N1] = NNZE;
}

__global__ __launch_bounds__(256)
void fill_kernel(const int* __restrict__ rows,
                 const int* __restrict__ cols,
                 const float* __restrict__ vals)
{
    int e = blockIdx.x * blockDim.x + threadIdx.x;
    if (e < NNZE) {
        int pos = atomicAdd(&g_cursor[rows[e]], 1);
        g_scol[pos] = cols[e];
        g_sval[pos] = vals[e];
    }
}

// ---------------------------------------------------------------------------
// Aggregation: one warp per output row, fp16 msg gather (16 B/lane/edge).
// Atomic-free, ELU fused, single fp32 write.
// ---------------------------------------------------------------------------
__global__ __launch_bounds__(256)
void aggregate_kernel(float* __restrict__ out)
{
    int row  = (blockIdx.x * blockDim.x + threadIdx.x) >> 5;
    int lane = threadIdx.x & 31;
    if (row >= N1) return;

    int beg = g_off[row];
    int end = g_off[row + 1];

    // Each lane owns 8 consecutive columns: [lane*8, lane*8+8)
    float acc[8];
    #pragma unroll
    for (int i = 0; i < 8; i++) acc[i] = 0.f;

    for (int e = beg; e < end; e++) {
        int   c = g_scol[e];
        float v = g_sval[e];
        const uint4* src = (const uint4*)(g_msg_h + (size_t)c * DOUT);
        uint4 p = src[lane];                    // 8 halves
        const __half2* hp = (const __half2*)&p;
        #pragma unroll
        for (int q = 0; q < 4; q++) {
            float2 f = __half22float2(hp[q]);
            acc[q * 2 + 0] = fmaf(v, f.x, acc[q * 2 + 0]);
            acc[q * 2 + 1] = fmaf(v, f.y, acc[q * 2 + 1]);
        }
    }

    #pragma unroll
    for (int i = 0; i < 8; i++)
        acc[i] = acc[i] > 0.f ? acc[i] : expm1f(acc[i]);

    float4* dst = (float4*)(out + (size_t)row * DOUT + lane * 8);
    dst[0] = make_float4(acc[0], acc[1], acc[2], acc[3]);
    dst[1] = make_float4(acc[4], acc[5], acc[6], acc[7]);
}

// ---------------------------------------------------------------------------
// Launch. Inputs: x_0, x_1(unused), nb_rows, nb_cols, nb_vals, weight.
// Output: float32 [N1, DOUT].
// ONLY change vs R14: CSR chain forked onto a side stream (graph fork/join
// via events) so its ~30 us of launches+work hide under the 113 us GEMM.
// Kernels themselves are byte-identical to R14.
// ---------------------------------------------------------------------------
extern "C" void kernel_launch(void* const* d_in, const int* in_sizes, int n_in,
                              void* d_out, int out_size)
{
    const float* x_0     = (const float*)d_in[0];
    const int*   nb_rows = (const int*)  d_in[2];
    const int*   nb_cols = (const int*)  d_in[3];
    const float* nb_vals = (const float*)d_in[4];
    const float* weight  = (const float*)d_in[5];
    float*       out     = (float*)d_out;

    static cudaStream_t s2 = nullptr;
    static cudaEvent_t evFork = nullptr, evJoin = nullptr;
    if (s2 == nullptr) {
        cudaStreamCreateWithFlags(&s2, cudaStreamNonBlocking);
        cudaEventCreateWithFlags(&evFork, cudaEventDisableTiming);
        cudaEventCreateWithFlags(&evJoin, cudaEventDisableTiming);
        cudaFuncSetAttribute(gemm_mma_kernel,
                             cudaFuncAttributeMaxDynamicSharedMemorySize, GEMM_SMEM);
    }

    // Fork side stream from the (capture) stream.
    cudaEventRecord(evFork, 0);
    cudaStreamWaitEvent(s2, evFork, 0);

    // Side stream: full CSR build (independent of GEMM).
    zero_count_kernel<<<(N1 + 255) / 256, 256, 0, s2>>>();
    count_kernel<<<(NNZE + 255) / 256, 256, 0, s2>>>(nb_rows);
    scan1_kernel<<<NB_SCAN, SCAN_B, 0, s2>>>();
    scan2_kernel<<<1, 256, 0, s2>>>();
    scan3_kernel<<<NB_SCAN, SCAN_B, 0, s2>>>();
    fill_kernel<<<(NNZE + 255) / 256, 256, 0, s2>>>(nb_rows, nb_cols, nb_vals);
    cudaEventRecord(evJoin, s2);

    // Main stream: W prep then the stable tensor-core GEMM (grid 2 x 782).
    wt_prep_kernel<<<(DIN * DOUT + 255) / 256, 256>>>(weight);
    dim3 ggrid(DOUT / 128, N0PAD / 128);
    gemm_mma_kernel<<<ggrid, 256, GEMM_SMEM>>>(x_0);

    // Join: aggregate needs both GEMM (stream order) and CSR (event).
    cudaStreamWaitEvent(0, evJoin, 0);
    int gblocks = (N1 * 32 + 255) / 256;
    aggregate_kernel<<<gblocks, 256>>>(out);
}